// round 15
// baseline (speedup 1.0000x reference)
#include <cuda_runtime.h>

// Problem constants (fixed shapes from reference)
#define BB 4
#define NN 19
#define HH 512
#define WW 512
#define HWc (HH * WW)          // 262144
#define CC 57
#define PAIRS (BB * NN)        // 76
#define THREADS 256

#define NDISK PAIRS                          // disk CTAs: blockIdx 0..75
#define NSTREAM 608                          // stream CTAs: 76..683
#define NWORK (NDISK + NSTREAM)              // 684 workers; watcher = 684
#define NV4 (BB * NN * (HWc / 4))            // 4,980,736 float4 of logits
#define TSTR (NSTREAM * THREADS)             // 155,648; NV4/TSTR = 32 exactly
#define PER_THREAD 32                        // float4 per stream thread
#define DEPTH 6                              // rolling prefetch distance

#define RAD 40
#define BBOX 81                              // 2*RAD+1
#define BBOX2 (BBOX * BBOX)                  // 6561

#define LOG2E 1.44269504088896340736f
#define LN2   0.69314718055994530942f

// Raw MUFU ops (no wrapper code, unlike __expf which adds an FMUL)
__device__ __forceinline__ float ex2_approx(float x) {
    float r;
    asm("ex2.approx.ftz.f32 %0, %1;" : "=f"(r) : "f"(x));
    return r;
}
__device__ __forceinline__ float lg2_approx(float x) {
    float r;
    asm("lg2.approx.ftz.f32 %0, %1;" : "=f"(r) : "f"(x));
    return r;
}

// Accumulators. Zero at module load; watcher resets after consuming ->
// state identical on every graph replay.
__device__ double g_shot;                    // global sum of bce hot terms
__device__ float g_bce[PAIRS];               // per-pair: -sum_heat(l)
__device__ float g_l1x[PAIRS];
__device__ float g_l1y[PAIRS];
__device__ float g_cnt[PAIRS];
__device__ unsigned int g_count = 0;

__global__ __launch_bounds__(THREADS, 5) void hm_main_kernel(
    const float* __restrict__ fm, const float* __restrict__ lms,
    float* __restrict__ out)
{
    const int warp = threadIdx.x >> 5;
    const int lane = threadIdx.x & 31;

    // ---------------- watcher CTA: finalize ----------------
    if (blockIdx.x == NWORK) {
        const int tid = threadIdx.x;
        if (tid == 0) {
            volatile unsigned int* vc = &g_count;
            while (*vc != (unsigned int)NWORK) __nanosleep(200);
        }
        __syncthreads();
        __threadfence();   // acquire: accumulator REDs visible after count

        float t = 0.0f;
        if (tid < PAIRS) {
            const float vb = __ldcg(&g_bce[tid]);     // = -sum_heat(l)
            const float vx = __ldcg(&g_l1x[tid]);
            const float vy = __ldcg(&g_l1y[tid]);
            const float vn = __ldcg(&g_cnt[tid]);
            t = 2.0f * vb * (1.0f / (float)HWc) + (vx + vy) / vn;
        }
        #pragma unroll
        for (int o = 16; o > 0; o >>= 1)
            t += __shfl_down_sync(0xFFFFFFFFu, t, o);

        __shared__ float s[8];
        if (lane == 0) s[warp] = t;
        __syncthreads();
        if (tid == 0) {
            float sum = 0.0f;
            #pragma unroll
            for (int i = 0; i < 8; i++) sum += s[i];
            // add the global hot-term once: 2*S_hot/HW (spread over all pairs)
            sum += (float)(2.0 * g_shot * (1.0 / (double)HWc));
            out[0] = sum / (float)PAIRS;
        }
        // reset state for the next graph replay (end state == initial state)
        if (tid < PAIRS) {
            g_bce[tid] = 0.0f; g_l1x[tid] = 0.0f;
            g_l1y[tid] = 0.0f; g_cnt[tid] = 0.0f;
        }
        if (tid == 0) { g_shot = 0.0; g_count = 0; }
        return;
    }

    // ---------------- disk CTAs (0..75): per-pair heat-region terms ----------------
    if (blockIdx.x < NDISK) {
        const int pair = blockIdx.x;             // 0..75
        const int b = pair / NN;
        const int n = pair % NN;
        const float lx = lms[pair * 2 + 0];
        const float ly = lms[pair * 2 + 1];
        const int x = (int)(lx * (float)HH);
        const int y = (int)(ly * (float)WW);

        const size_t base = ((size_t)(b * CC + n)) * (size_t)HWc;
        const float* __restrict__ pL = fm + base;
        const float* __restrict__ pX = fm + base + (size_t)NN * HWc;
        const float* __restrict__ pY = fm + base + (size_t)(2 * NN) * HWc;

        float subL = 0.0f, l1x = 0.0f, l1y = 0.0f;
        int cnt = 0;

        for (int idx = threadIdx.x; idx < BBOX2; idx += THREADS) {
            const int r  = idx / BBOX;       // 0..80
            const int cc = idx - r * BBOX;   // 0..80
            const int di = r - RAD;
            const int dj = cc - RAD;
            const int gi = x + di;
            const int gj = y + dj;
            if ((unsigned)gi < HH && (unsigned)gj < WW &&
                di * di + dj * dj <= RAD * RAD) {
                const int off = gi * WW + gj;
                const float l  = __ldg(pL + off);
                const float px = __ldg(pX + off);
                const float py = __ldg(pY + off);
                subL += l;
                l1x += fabsf(px + (float)di * (1.0f / 40.0f));  // |px - (-di/40)|
                l1y += fabsf(py + (float)dj * (1.0f / 40.0f));
                cnt++;
            }
        }

        float c = (float)cnt;
        float nb = -subL;   // contribution to bce: -sum_heat(l)
        #pragma unroll
        for (int o = 16; o > 0; o >>= 1) {
            nb  += __shfl_down_sync(0xFFFFFFFFu, nb, o);
            l1x += __shfl_down_sync(0xFFFFFFFFu, l1x, o);
            l1y += __shfl_down_sync(0xFFFFFFFFu, l1y, o);
            c   += __shfl_down_sync(0xFFFFFFFFu, c, o);
        }
        __shared__ float d0[8], d1[8], d2[8], d3[8];
        if (lane == 0) { d0[warp] = nb; d1[warp] = l1x; d2[warp] = l1y; d3[warp] = c; }
        __syncthreads();
        if (threadIdx.x == 0) {
            float v0 = 0.f, v1 = 0.f, v2 = 0.f, v3 = 0.f;
            #pragma unroll
            for (int i = 0; i < 8; i++) {
                v0 += d0[i]; v1 += d1[i]; v2 += d2[i]; v3 += d3[i];
            }
            atomicAdd(&g_bce[pair], v0);
            atomicAdd(&g_l1x[pair], v1);
            atomicAdd(&g_l1y[pair], v2);
            atomicAdd(&g_cnt[pair], v3);
            __threadfence();
            atomicAdd(&g_count, 1u);
        }
        return;
    }

    // ---------------- stream CTAs (76..683): flat bce hot-term sum ----------------
    // Each thread: exactly 32 float4. Rolling ring of 6 buffers keeps ~6 LDG.128
    // in flight per thread; occ 5 CTAs/SM -> 40 warps -> 30KB in flight per SM.
    const float4* __restrict__ pL = (const float4*)fm;

    float bce_lin = 0.0f;    // Sum of (l + |l|)  == 2*max(l,0)
    float bce_log2 = 0.0f;   // Sum of log2(1+2^(-|l|*log2e)); *LN2 at the end

    const int i0 = (blockIdx.x - NDISK) * THREADS + threadIdx.x;

    float4 buf[DEPTH];
    #pragma unroll
    for (int j = 0; j < DEPTH; j++)
        buf[j] = __ldcs(pL + i0 + j * TSTR);

    #pragma unroll
    for (int k = 0; k < PER_THREAD; k++) {
        const float4 L = buf[k % DEPTH];
        if (k + DEPTH < PER_THREAD)
            buf[k % DEPTH] = __ldcs(pL + i0 + (k + DEPTH) * TSTR);

        const float a0 = fabsf(L.x), a1 = fabsf(L.y);
        const float a2 = fabsf(L.z), a3 = fabsf(L.w);
        bce_lin += ((L.x + a0) + (L.y + a1)) + ((L.z + a2) + (L.w + a3));
        const float e0 = 1.0f + ex2_approx(a0 * -LOG2E);
        const float e1 = 1.0f + ex2_approx(a1 * -LOG2E);
        const float e2 = 1.0f + ex2_approx(a2 * -LOG2E);
        const float e3 = 1.0f + ex2_approx(a3 * -LOG2E);
        bce_log2 += lg2_approx((e0 * e1) * (e2 * e3));
    }

    // bce partial = 0.5*sum(l+|l|) + ln2*sum(log2 terms)
    float bce = fmaf(0.5f, bce_lin, bce_log2 * LN2);

    #pragma unroll
    for (int o = 16; o > 0; o >>= 1)
        bce += __shfl_down_sync(0xFFFFFFFFu, bce, o);

    __shared__ float s0[8];
    if (lane == 0) s0[warp] = bce;
    __syncthreads();
    // warps 1..7 retire here; only thread0 pays the fence.

    if (threadIdx.x == 0) {
        float v0 = 0.f;
        #pragma unroll
        for (int i2 = 0; i2 < 8; i2++) v0 += s0[i2];
        atomicAdd(&g_shot, (double)v0);  // fire-and-forget, single scalar
        __threadfence();                 // order data RED before the count RED
        atomicAdd(&g_count, 1u);
    }
}

extern "C" void kernel_launch(void* const* d_in, const int* in_sizes, int n_in,
                              void* d_out, int out_size)
{
    const float* fm  = (const float*)d_in[0];   // feature_maps (4,57,512,512) f32
    const float* lms = (const float*)d_in[1];   // landmarks (4,19,2) f32
    float* out = (float*)d_out;

    hm_main_kernel<<<NWORK + 1, THREADS>>>(fm, lms, out);
}

// round 16
// speedup vs baseline: 1.2411x; 1.2411x over previous
#include <cuda_runtime.h>

// Problem constants (fixed shapes from reference)
#define BB 4
#define NN 19
#define HH 512
#define WW 512
#define HWc (HH * WW)          // 262144
#define CC 57
#define PAIRS (BB * NN)        // 76
#define THREADS 256

#define NDISK PAIRS                          // disk CTAs: blockIdx 0..75
#define NSTREAM 608                          // stream CTAs: 76..683
#define NWORK (NDISK + NSTREAM)              // 684 workers; watcher = 684
#define NV4 (BB * NN * (HWc / 4))            // 4,980,736 float4 of logits
#define TSTR (NSTREAM * THREADS)             // 155,648; NV4/TSTR = 32 exactly
#define PER_THREAD 32                        // float4 per stream thread
#define DEPTH 4                              // rolling prefetch distance (power of 2!)

#define RAD 40
#define BBOX 81                              // 2*RAD+1
#define BBOX2 (BBOX * BBOX)                  // 6561

// Accumulators. Zero at module load; watcher resets after consuming ->
// state identical on every graph replay.
__device__ double g_shot;                    // global sum of bce hot terms
__device__ float g_bce[PAIRS];               // per-pair: -sum_heat(l)
__device__ float g_l1x[PAIRS];
__device__ float g_l1y[PAIRS];
__device__ float g_cnt[PAIRS];
__device__ unsigned int g_count = 0;

__global__ __launch_bounds__(THREADS, 5) void hm_main_kernel(
    const float* __restrict__ fm, const float* __restrict__ lms,
    float* __restrict__ out)
{
    const int warp = threadIdx.x >> 5;
    const int lane = threadIdx.x & 31;

    // ---------------- watcher CTA: finalize ----------------
    if (blockIdx.x == NWORK) {
        const int tid = threadIdx.x;
        if (tid == 0) {
            volatile unsigned int* vc = &g_count;
            while (*vc != (unsigned int)NWORK) __nanosleep(200);
        }
        __syncthreads();
        __threadfence();   // acquire: accumulator REDs visible after count

        float t = 0.0f;
        if (tid < PAIRS) {
            const float vb = __ldcg(&g_bce[tid]);     // = -sum_heat(l)
            const float vx = __ldcg(&g_l1x[tid]);
            const float vy = __ldcg(&g_l1y[tid]);
            const float vn = __ldcg(&g_cnt[tid]);
            t = 2.0f * vb * (1.0f / (float)HWc) + (vx + vy) / vn;
        }
        #pragma unroll
        for (int o = 16; o > 0; o >>= 1)
            t += __shfl_down_sync(0xFFFFFFFFu, t, o);

        __shared__ float s[8];
        if (lane == 0) s[warp] = t;
        __syncthreads();
        if (tid == 0) {
            float sum = 0.0f;
            #pragma unroll
            for (int i = 0; i < 8; i++) sum += s[i];
            // add the global hot-term once: 2*S_hot/HW (spread over all pairs)
            sum += (float)(2.0 * g_shot * (1.0 / (double)HWc));
            out[0] = sum / (float)PAIRS;
        }
        // reset state for the next graph replay (end state == initial state)
        if (tid < PAIRS) {
            g_bce[tid] = 0.0f; g_l1x[tid] = 0.0f;
            g_l1y[tid] = 0.0f; g_cnt[tid] = 0.0f;
        }
        if (tid == 0) { g_shot = 0.0; g_count = 0; }
        return;
    }

    // ---------------- disk CTAs (0..75): per-pair heat-region terms ----------------
    if (blockIdx.x < NDISK) {
        const int pair = blockIdx.x;             // 0..75
        const int b = pair / NN;
        const int n = pair % NN;
        const float lx = lms[pair * 2 + 0];
        const float ly = lms[pair * 2 + 1];
        const int x = (int)(lx * (float)HH);
        const int y = (int)(ly * (float)WW);

        const size_t base = ((size_t)(b * CC + n)) * (size_t)HWc;
        const float* __restrict__ pL = fm + base;
        const float* __restrict__ pX = fm + base + (size_t)NN * HWc;
        const float* __restrict__ pY = fm + base + (size_t)(2 * NN) * HWc;

        float subL = 0.0f, l1x = 0.0f, l1y = 0.0f;
        int cnt = 0;

        for (int idx = threadIdx.x; idx < BBOX2; idx += THREADS) {
            const int r  = idx / BBOX;       // 0..80
            const int cc = idx - r * BBOX;   // 0..80
            const int di = r - RAD;
            const int dj = cc - RAD;
            const int gi = x + di;
            const int gj = y + dj;
            if ((unsigned)gi < HH && (unsigned)gj < WW &&
                di * di + dj * dj <= RAD * RAD) {
                const int off = gi * WW + gj;
                const float l  = __ldg(pL + off);
                const float px = __ldg(pX + off);
                const float py = __ldg(pY + off);
                subL += l;
                l1x += fabsf(px + (float)di * (1.0f / 40.0f));  // |px - (-di/40)|
                l1y += fabsf(py + (float)dj * (1.0f / 40.0f));
                cnt++;
            }
        }

        float c = (float)cnt;
        float nb = -subL;   // contribution to bce: -sum_heat(l)
        #pragma unroll
        for (int o = 16; o > 0; o >>= 1) {
            nb  += __shfl_down_sync(0xFFFFFFFFu, nb, o);
            l1x += __shfl_down_sync(0xFFFFFFFFu, l1x, o);
            l1y += __shfl_down_sync(0xFFFFFFFFu, l1y, o);
            c   += __shfl_down_sync(0xFFFFFFFFu, c, o);
        }
        __shared__ float d0[8], d1[8], d2[8], d3[8];
        if (lane == 0) { d0[warp] = nb; d1[warp] = l1x; d2[warp] = l1y; d3[warp] = c; }
        __syncthreads();
        if (threadIdx.x == 0) {
            float v0 = 0.f, v1 = 0.f, v2 = 0.f, v3 = 0.f;
            #pragma unroll
            for (int i = 0; i < 8; i++) {
                v0 += d0[i]; v1 += d1[i]; v2 += d2[i]; v3 += d3[i];
            }
            atomicAdd(&g_bce[pair], v0);
            atomicAdd(&g_l1x[pair], v1);
            atomicAdd(&g_l1y[pair], v2);
            atomicAdd(&g_cnt[pair], v3);
            __threadfence();
            atomicAdd(&g_count, 1u);
        }
        return;
    }

    // ---------------- stream CTAs (76..683): flat bce hot-term sum ----------------
    // Each thread: exactly 32 float4. Rolling ring of 4 buffers (power-of-2
    // modulus -> fully static indexing) keeps a steady 4 LDG.128 in flight;
    // occ 5 CTAs/SM -> 40 warps -> ~20KB in flight per SM.
    const float4* __restrict__ pL = (const float4*)fm;

    float bce_lin = 0.0f;   // Sum of (l + |l|)  == 2*max(l,0)
    float bce_log = 0.0f;   // Sum of log(1+exp(-|l|)) via log-of-products

    const int i0 = (blockIdx.x - NDISK) * THREADS + threadIdx.x;

    float4 buf[DEPTH];
    #pragma unroll
    for (int j = 0; j < DEPTH; j++)
        buf[j] = __ldcs(pL + i0 + j * TSTR);

    #pragma unroll
    for (int k = 0; k < PER_THREAD; k++) {
        const float4 L = buf[k & (DEPTH - 1)];
        if (k + DEPTH < PER_THREAD)
            buf[k & (DEPTH - 1)] = __ldcs(pL + i0 + (k + DEPTH) * TSTR);

        const float a0 = fabsf(L.x), a1 = fabsf(L.y);
        const float a2 = fabsf(L.z), a3 = fabsf(L.w);
        bce_lin += ((L.x + a0) + (L.y + a1)) + ((L.z + a2) + (L.w + a3));
        const float e0 = 1.0f + __expf(-a0);
        const float e1 = 1.0f + __expf(-a1);
        const float e2 = 1.0f + __expf(-a2);
        const float e3 = 1.0f + __expf(-a3);
        bce_log += __logf((e0 * e1) * (e2 * e3));
    }

    float bce = fmaf(0.5f, bce_lin, bce_log);

    #pragma unroll
    for (int o = 16; o > 0; o >>= 1)
        bce += __shfl_down_sync(0xFFFFFFFFu, bce, o);

    __shared__ float s0[8];
    if (lane == 0) s0[warp] = bce;
    __syncthreads();
    // warps 1..7 retire here; only thread0 pays the fence.

    if (threadIdx.x == 0) {
        float v0 = 0.f;
        #pragma unroll
        for (int i2 = 0; i2 < 8; i2++) v0 += s0[i2];
        atomicAdd(&g_shot, (double)v0);  // fire-and-forget, single scalar
        __threadfence();                 // order data RED before the count RED
        atomicAdd(&g_count, 1u);
    }
}

extern "C" void kernel_launch(void* const* d_in, const int* in_sizes, int n_in,
                              void* d_out, int out_size)
{
    const float* fm  = (const float*)d_in[0];   // feature_maps (4,57,512,512) f32
    const float* lms = (const float*)d_in[1];   // landmarks (4,19,2) f32
    float* out = (float*)d_out;

    hm_main_kernel<<<NWORK + 1, THREADS>>>(fm, lms, out);
}